// round 8
// baseline (speedup 1.0000x reference)
#include <cuda_runtime.h>
#include <math.h>

#define NB     1805          // 5*19*19 boxes per batch
#define NBP    1824
#define SORTC  1024          // bitonic capacity (M ~= 900 for this data)
#define NW64   29            // ceil(1805/64) u64 words per mask row
#define NW32   58
#define NBLK   64
#define NTHR   512
#define BPB    8             // blocks per batch

// SoA decoded boxes (indexed by rank)
__device__ float g_bx1[8][NBP], g_bx2[8][NBP];
__device__ float g_by1[8][NBP], g_by2[8][NBP];
__device__ float g_bw [8][NBP], g_bh [8][NBP];
__device__ int   g_M[8];
__device__ unsigned long long g_mask[8ULL * NB * NW64];  // zero-init
__device__ unsigned long long g_gtm[8][50][NW64];
__device__ int      g_part[8][3];
__device__ int      g_ticket = 0;
__device__ unsigned g_relA[8];      // boxes-ready release (monotone)
__device__ unsigned g_relB[8];      // masks-done release (monotone)
__device__ unsigned g_cntB[8];      // masks-done arrivals (self-reset)

__constant__ float ANCW[5] = {1.3221f, 3.19275f, 5.05587f, 9.47112f, 11.2364f};
__constant__ float ANCH[5] = {1.73145f, 4.00944f, 8.09892f, 4.84053f, 10.0071f};

// IoU > thr with explicit RN ops + IEEE div (matches jax f32; uarea=0 -> NaN -> false)
__device__ __forceinline__ bool iou_gt(
    float ax1, float ax2, float ay1, float ay2, float aw, float ah,
    float bx1, float bx2, float by1, float by2, float bw, float bh, float thr) {
    float uw = __fsub_rn(fmaxf(ax2, bx2), fminf(ax1, bx1));
    float uh = __fsub_rn(fmaxf(ay2, by2), fminf(ay1, by1));
    float cw = __fsub_rn(__fadd_rn(aw, bw), uw);
    float ch = __fsub_rn(__fadd_rn(ah, bh), uh);
    float carea = (cw > 0.0f && ch > 0.0f) ? __fmul_rn(cw, ch) : 0.0f;
    float uarea = __fsub_rn(__fadd_rn(__fmul_rn(aw, ah), __fmul_rn(bw, bh)), carea);
    return __fdiv_rn(carea, uarea) > thr;
}

extern "C" __global__ void __launch_bounds__(NTHR)
fused_kernel(const float* __restrict__ out,    // [8,125,19,19]
             const float* __restrict__ tgt,    // [8,250]
             float* __restrict__ outp)         // [6]
{
    __shared__ unsigned long long slist[SORTC];
    __shared__ float sg[252];
    __shared__ unsigned long long skeep[32];
    __shared__ unsigned long long sGV;
    __shared__ int sCnt, sTot, sProp, sCorr;

    const int blk = blockIdx.x;          // 0..63
    const int tid = threadIdx.x;
    const int lane = tid & 31, warp = tid >> 5;
    const int b = blk >> 3, k = blk & 7; // batch, block-within-batch

    volatile unsigned* relA = (volatile unsigned*)&g_relA[b];
    volatile unsigned* relB = (volatile unsigned*)&g_relB[b];
    const unsigned r0a = *relA;          // capture BEFORE any producer can bump
    const unsigned r0b = *relB;

    // ================= Phase A (block 0 only): compact+sort+decode =======
    if (k == 0) {
        const float* ob = out + (size_t)b * 125 * 361;
        if (tid == 0) sCnt = 0;
        for (int t = tid; t < 250; t += NTHR) sg[t] = tgt[b * 250 + t];
        __syncthreads();

        // ballot-compact valid keys as u64 (key bits << 32 | (NB - idx))
        for (int r0 = 0; r0 < NB; r0 += NTHR) {
            int r = r0 + tid;
            bool v = false;
            unsigned long long k64 = 0ULL;
            if (r < NB) {
                int a = r / 361, rem = r - a * 361;
                float kk = ob[(a * 25 + 4) * 361 + rem];
                if (kk > 0.0f) {
                    v = true;
                    k64 = ((unsigned long long)__float_as_uint(kk) << 32)
                        | (unsigned)(NB - r);
                }
            }
            unsigned bal = __ballot_sync(0xffffffffu, v);
            int base = 0;
            if (lane == 0 && bal) base = atomicAdd(&sCnt, __popc(bal));
            base = __shfl_sync(0xffffffffu, base, 0);
            if (v) slist[base + __popc(bal & ((1u << lane) - 1u))] = k64;
        }
        __syncthreads();
        const int M = sCnt;
        for (int r = M + tid; r < SORTC; r += NTHR) slist[r] = 0ULL;  // pad
        if (tid == 0) g_M[b] = M;
        __syncthreads();

        // bitonic sort desc, 1024 elems, 512 threads (55 steps)
        for (int kk = 2; kk <= SORTC; kk <<= 1) {
            for (int j = kk >> 1; j > 0; j >>= 1) {
                int i = ((tid & ~(j - 1)) << 1) | (tid & (j - 1));
                int p = i | j;
                bool up = (i & kk) == 0;
                unsigned long long a = slist[i], c = slist[p];
                if (up ? (a < c) : (a > c)) { slist[i] = c; slist[p] = a; }
                __syncthreads();
            }
        }

        // decode rank -> SoA
        for (int r = tid; r < M; r += NTHR) {
            int i = NB - (int)(unsigned)(slist[r] & 0xffffffffULL);
            int a = i / 361, rem = i - a * 361;
            int hh = rem / 19, ww = rem - hh * 19;
            const float* p = ob + (a * 25) * 361 + rem;
            float cx = (1.0f / (1.0f + expf(-p[0]))   + (float)ww) / 19.0f;
            float cy = (1.0f / (1.0f + expf(-p[361])) + (float)hh) / 19.0f;
            float bw = expf(p[722])  * (ANCW[a] / 19.0f);
            float bh = expf(p[1083]) * (ANCH[a] / 19.0f);
            g_bx1[b][r] = cx - bw * 0.5f;
            g_bx2[b][r] = cx + bw * 0.5f;
            g_by1[b][r] = cy - bh * 0.5f;
            g_by2[b][r] = cy + bh * 0.5f;
            g_bw [b][r] = bw;
            g_bh [b][r] = bh;
        }
        __threadfence();
        __syncthreads();
        if (tid == 0) atomicAdd(&g_relA[b], 1u);   // release boxes-ready
    } else {
        // blocks 1..7 wait for boxes
        if (tid == 0) { while (*relA == r0a) __nanosleep(64); }
        __syncthreads();
        __threadfence();
    }

    // ================= Phase B: masks (all 8 blocks of batch) ============
    {
        const int M = g_M[b];
        const int nw32 = (M + 31) >> 5;

        if (k > 0) {                      // 112 warps: box-vs-box masks
            const int wq = (k - 1) * 16 + warp;
            unsigned* mask32 = (unsigned*)g_mask;
            const int G = (M + 3) >> 2;
            for (int g = wq; g < G; g += 112) {
                int r0 = g << 2;
                float rx1[4], rx2[4], ry1[4], ry2[4], rw[4], rh[4];
                #pragma unroll
                for (int d = 0; d < 4; d++) {
                    int ii = min(r0 + d, M - 1);
                    rx1[d] = g_bx1[b][ii]; rx2[d] = g_bx2[b][ii];
                    ry1[d] = g_by1[b][ii]; ry2[d] = g_by2[b][ii];
                    rw[d]  = g_bw [b][ii]; rh[d]  = g_bh [b][ii];
                }
                #pragma unroll 2
                for (int w = r0 >> 5; w < nw32; w++) {
                    int j = (w << 5) + lane, jc = min(j, M - 1);
                    float cx1 = g_bx1[b][jc], cx2 = g_bx2[b][jc];
                    float cy1 = g_by1[b][jc], cy2 = g_by2[b][jc];
                    float cw_ = g_bw [b][jc], ch_ = g_bh [b][jc];
                    #pragma unroll
                    for (int d = 0; d < 4; d++) {
                        int ii = r0 + d;
                        bool sp = (j > ii) && (j < M) && (ii < M) &&
                                  iou_gt(rx1[d], rx2[d], ry1[d], ry2[d], rw[d], rh[d],
                                         cx1, cx2, cy1, cy2, cw_, ch_, 0.45f);
                        unsigned bal = __ballot_sync(0xffffffffu, sp);
                        if (lane == d && ii < M)
                            mask32[((size_t)(b * NB + ii)) * NW32 + w] = bal;
                    }
                }
            }
        } else {                          // block 0's 16 warps: GT masks
            if (tid == 32 + 1) {          // one thread: GT validity + total
                unsigned long long gv = 0ULL;
                int v = 1, tb = 0;
                for (int t = 0; t < 50; t++) {
                    if (sg[t * 5 + 1] == 0.0f) v = 0;
                    gv |= (unsigned long long)v << t; tb += v;
                }
                sGV = gv; sTot = tb;
            }
            unsigned* gtm32 = (unsigned*)g_gtm;
            const int ntasks = 50 * nw32;
            for (int task = warp; task < ntasks; task += 16) {
                int t = task / nw32, w = task - t * nw32;
                float gx = sg[t * 5 + 1], gy = sg[t * 5 + 2];
                float gw = sg[t * 5 + 3], gh = sg[t * 5 + 4];
                float gx1 = gx - gw * 0.5f, gx2 = gx + gw * 0.5f;
                float gy1 = gy - gh * 0.5f, gy2 = gy + gh * 0.5f;
                int j = (w << 5) + lane, jc = min(j, M - 1);
                float cx1 = g_bx1[b][jc], cx2 = g_bx2[b][jc];
                float cy1 = g_by1[b][jc], cy2 = g_by2[b][jc];
                float cw_ = g_bw [b][jc], ch_ = g_bh [b][jc];
                bool sp = (j < M) &&
                          iou_gt(gx1, gx2, gy1, gy2, gw, gh,
                                 cx1, cx2, cy1, cy2, cw_, ch_, 0.5f);
                unsigned bal = __ballot_sync(0xffffffffu, sp);
                if (lane == 0)
                    gtm32[((size_t)(b * 50 + t)) * NW32 + w] = bal;
            }
        }

        // per-batch masks-done arrival
        __threadfence();
        __syncthreads();
        if (tid == 0) {
            unsigned old = atomicAdd(&g_cntB[b], 1u);
            if (old == BPB - 1) {
                g_cntB[b] = 0;
                __threadfence();
                atomicAdd(&g_relB[b], 1u);
            }
        }
        if (k > 0) return;                // only block 0 continues
        if (tid == 0) { while (*relB == r0b) __nanosleep(64); }
        __syncthreads();
        __threadfence();
    }

    // ================= Phase C (block 0): serial chain + stats ===========
    {
        const int M = g_M[b];
        if (tid == 0) sCorr = 0;
        __syncthreads();

        if (warp == 0) {                 // greedy NMS, 8-box chunks, mod-3 bufs
            const unsigned long long* mb = g_mask + (size_t)b * NB * NW64;
            const bool ld = (lane < NW64);
            unsigned long long removed = 0ULL;
            unsigned long long buf[3][8];
            #pragma unroll
            for (int ph = 0; ph < 3; ph++)
                #pragma unroll
                for (int d = 0; d < 8; d++) {
                    int r = ph * 8 + d;
                    buf[ph][d] = (ld && r < M) ? mb[(size_t)r * NW64 + lane] : 0ULL;
                }
            for (int base = 0; base < M; base += 24) {
                #pragma unroll
                for (int ph = 0; ph < 3; ph++) {
                    int bb = base + ph * 8;
                    if (bb < M) {
                        int w0 = bb >> 6, sh = bb & 63;
                        unsigned long long sub = 0ULL;   // 8x8 intra submatrix
                        #pragma unroll
                        for (int d = 0; d < 8; d++)
                            sub |= ((buf[ph][d] >> sh) & 0xFFULL) << (8 * d);
                        unsigned long long sub_b = __shfl_sync(0xffffffffu, sub, w0);
                        unsigned long long rw    = __shfl_sync(0xffffffffu, removed, w0);
                        unsigned supp = (unsigned)((rw >> sh) & 0xFFULL);
                        unsigned dec = 0;
                        int lim = min(8, M - bb);
                        #pragma unroll
                        for (int d = 0; d < 8; d++)
                            if (d < lim && !((supp >> d) & 1u)) {
                                dec  |= 1u << d;
                                supp |= (unsigned)((sub_b >> (8 * d)) & 0xFFULL);
                            }
                        #pragma unroll
                        for (int d = 0; d < 8; d++)
                            if (dec & (1u << d)) removed |= buf[ph][d];
                        int nb2 = bb + 24;
                        #pragma unroll
                        for (int d = 0; d < 8; d++)
                            buf[ph][d] = (ld && nb2 + d < M)
                                       ? mb[(size_t)(nb2 + d) * NW64 + lane] : 0ULL;
                    }
                }
            }
            skeep[lane] = ld ? removed : 0ULL;
            int pc = ld ? __popcll(removed) : 0;
            #pragma unroll
            for (int o = 16; o; o >>= 1) pc += __shfl_xor_sync(0xffffffffu, pc, o);
            if (lane == 0) sProp = M - pc;
        }
        __syncthreads();

        // correct: one lane per GT, AND precomputed masks vs kept set
        if (tid < 50 && ((sGV >> tid) & 1ULL)) {
            const unsigned long long* gm = g_gtm[b][tid];
            bool any = false;
            #pragma unroll
            for (int w = 0; w < NW64; w++)
                any |= (gm[w] & ~skeep[w]) != 0ULL;
            if (any) atomicAdd(&sCorr, 1);
        }
        __syncthreads();

        if (tid == 0) {
            g_part[b][0] = sTot; g_part[b][1] = sProp; g_part[b][2] = sCorr;
            __threadfence();
            int tk = atomicAdd(&g_ticket, 1);
            if (tk == 7) {               // last batch finalizes
                __threadfence();
                int T = 0, P = 0, C = 0;
                for (int i = 0; i < 8; i++) {
                    T += g_part[i][0]; P += g_part[i][1]; C += g_part[i][2];
                }
                float tf = (float)T, pf = (float)P, cf = (float)C;
                float prec = cf / (pf + 1e-6f);
                float rec  = cf / (tf + 1e-6f);
                float f    = 2.0f * prec * rec / (prec + rec + 1e-6f);
                outp[0] = tf; outp[1] = pf; outp[2] = cf;
                outp[3] = prec; outp[4] = rec; outp[5] = f;
                atomicExch(&g_ticket, 0); // reset for next replay
            }
        }
    }
}

extern "C" void kernel_launch(void* const* d_in, const int* in_sizes, int n_in,
                              void* d_out, int out_size) {
    const float* output = (const float*)d_in[0];  // [8,125,19,19]
    const float* target = (const float*)d_in[1];  // [8,250]
    fused_kernel<<<NBLK, NTHR>>>(output, target, (float*)d_out);
}

// round 9
// speedup vs baseline: 1.0267x; 1.0267x over previous
#include <cuda_runtime.h>
#include <math.h>

#define NB     1805          // 5*19*19 boxes per batch
#define NBP    1824
#define NW64   29            // ceil(1805/64) u64 words per mask row
#define NW32   58
#define NBLK   64
#define NTHR   512
#define BPB    8             // blocks per batch
#define NCH8   228           // NBP/8 chunks

// SoA decoded boxes (indexed by rank)
__device__ float g_bx1[8][NBP], g_bx2[8][NBP];
__device__ float g_by1[8][NBP], g_by2[8][NBP];
__device__ float g_bw [8][NBP], g_bh [8][NBP];
__device__ int   g_M[8];
__device__ unsigned long long g_mask[8ULL * NB * NW64];  // zero-init
__device__ unsigned long long g_intra[8][NCH8];          // 8x8 intra-chunk bytes
__device__ unsigned long long g_gtm[8][50][NW64];
__device__ int      g_part[8][3];
__device__ int      g_ticket = 0;
__device__ unsigned g_relA[8], g_cntA[8];
__device__ unsigned g_relB[8], g_cntB[8];

__constant__ float ANCW[5] = {1.3221f, 3.19275f, 5.05587f, 9.47112f, 11.2364f};
__constant__ float ANCH[5] = {1.73145f, 4.00944f, 8.09892f, 4.84053f, 10.0071f};

// IoU > thr with explicit RN ops + IEEE div (matches jax f32; uarea=0 -> NaN -> false)
__device__ __forceinline__ bool iou_gt(
    float ax1, float ax2, float ay1, float ay2, float aw, float ah,
    float bx1, float bx2, float by1, float by2, float bw, float bh, float thr) {
    float uw = __fsub_rn(fmaxf(ax2, bx2), fminf(ax1, bx1));
    float uh = __fsub_rn(fmaxf(ay2, by2), fminf(ay1, by1));
    float cw = __fsub_rn(__fadd_rn(aw, bw), uw);
    float ch = __fsub_rn(__fadd_rn(ah, bh), uh);
    float carea = (cw > 0.0f && ch > 0.0f) ? __fmul_rn(cw, ch) : 0.0f;
    float uarea = __fsub_rn(__fadd_rn(__fmul_rn(aw, ah), __fmul_rn(bw, bh)), carea);
    return __fdiv_rn(carea, uarea) > thr;
}

extern "C" __global__ void __launch_bounds__(NTHR)
fused_kernel(const float* __restrict__ out,    // [8,125,19,19]
             const float* __restrict__ tgt,    // [8,250]
             float* __restrict__ outp)         // [6]
{
    __shared__ unsigned long long slist[NBP + 8];
    __shared__ float sg[252];
    __shared__ unsigned long long skeep[32];
    __shared__ unsigned long long sGV;
    __shared__ int sCnt, sTot, sProp, sCorr;

    const int blk = blockIdx.x;          // 0..63
    const int tid = threadIdx.x;
    const int lane = tid & 31, warp = tid >> 5;
    const int b = blk >> 3, k = blk & 7;

    volatile unsigned* relA = (volatile unsigned*)&g_relA[b];
    volatile unsigned* relB = (volatile unsigned*)&g_relB[b];
    const unsigned r0a = *relA;          // capture at entry (replay-safe)
    const unsigned r0b = *relB;

    // ================= Phase A (all 8 blocks): compact + rank + decode ===
    {
        const float* ob = out + (size_t)b * 125 * 361;
        if (tid == 0) sCnt = 0;
        if (k == 0)
            for (int t = tid; t < 250; t += NTHR) sg[t] = tgt[b * 250 + t];
        __syncthreads();

        // redundant ballot-compact of valid keys as u64 (key<<32 | NB-idx)
        for (int r0 = 0; r0 < NB; r0 += NTHR) {
            int r = r0 + tid;
            bool v = false;
            unsigned long long k64 = 0ULL;
            if (r < NB) {
                int a = r / 361, rem = r - a * 361;
                float kk = ob[(a * 25 + 4) * 361 + rem];
                if (kk > 0.0f) {                      // sigmoid > 0.5
                    v = true;
                    k64 = ((unsigned long long)__float_as_uint(kk) << 32)
                        | (unsigned)(NB - r);
                }
            }
            unsigned bal = __ballot_sync(0xffffffffu, v);
            int base = 0;
            if (lane == 0 && bal) base = atomicAdd(&sCnt, __popc(bal));
            base = __shfl_sync(0xffffffffu, base, 0);
            if (v) slist[base + __popc(bal & ((1u << lane) - 1u))] = k64;
        }
        __syncthreads();
        const int M = sCnt;
        if (k == 0 && tid == 0) g_M[b] = M;
        if (tid < 8) slist[M + tid] = 0ULL;           // pad
        __syncthreads();
        const int Mp = (M + 3) & ~3;

        // rank + decode: deterministic original-index slice [k*226, k*226+226)
        int i = k * 226 + tid;
        if (tid < 226 && i < NB) {
            int a = i / 361, rem = i - a * 361;
            float ki = ob[(a * 25 + 4) * 361 + rem];
            if (ki > 0.0f) {
                unsigned long long k64 =
                    ((unsigned long long)__float_as_uint(ki) << 32)
                    | (unsigned)(NB - i);
                const ulonglong2* l2 = (const ulonglong2*)slist;
                int rank = 0;
                #pragma unroll 4
                for (int w = 0; w < (Mp >> 1); w += 2) {
                    ulonglong2 p = l2[w], q = l2[w + 1];
                    rank += (p.x > k64) + (p.y > k64) + (q.x > k64) + (q.y > k64);
                }
                int hh = rem / 19, ww = rem - hh * 19;
                const float* p = ob + (a * 25) * 361 + rem;
                float cx = (1.0f / (1.0f + expf(-p[0]))   + (float)ww) / 19.0f;
                float cy = (1.0f / (1.0f + expf(-p[361])) + (float)hh) / 19.0f;
                float bw = expf(p[722])  * (ANCW[a] / 19.0f);
                float bh = expf(p[1083]) * (ANCH[a] / 19.0f);
                g_bx1[b][rank] = cx - bw * 0.5f;
                g_bx2[b][rank] = cx + bw * 0.5f;
                g_by1[b][rank] = cy - bh * 0.5f;
                g_by2[b][rank] = cy + bh * 0.5f;
                g_bw [b][rank] = bw;
                g_bh [b][rank] = bh;
            }
        }
        __threadfence();
        __syncthreads();
        if (tid == 0) {
            unsigned old = atomicAdd(&g_cntA[b], 1u);
            if (old == BPB - 1) {
                g_cntA[b] = 0;
                __threadfence();
                atomicAdd(&g_relA[b], 1u);
            }
            while (*relA == r0a) __nanosleep(64);
        }
        __syncthreads();
        __threadfence();
    }

    // ================= Phase B: masks (8 blocks per batch) ===============
    {
        const int M = g_M[b];
        const int nw32 = (M + 31) >> 5;

        if (k > 0) {                      // 112 warps: box-vs-box + intra bytes
            const int wq = (k - 1) * 16 + warp;
            unsigned* mask32 = (unsigned*)g_mask;
            unsigned char* intra8 = (unsigned char*)&g_intra[b][0];
            const int G = (M + 3) >> 2;
            for (int g = wq; g < G; g += 112) {
                int r0 = g << 2;
                float rx1[4], rx2[4], ry1[4], ry2[4], rw[4], rh[4];
                #pragma unroll
                for (int d = 0; d < 4; d++) {
                    int ii = min(r0 + d, M - 1);
                    rx1[d] = g_bx1[b][ii]; rx2[d] = g_bx2[b][ii];
                    ry1[d] = g_by1[b][ii]; ry2[d] = g_by2[b][ii];
                    rw[d]  = g_bw [b][ii]; rh[d]  = g_bh [b][ii];
                }
                const int wlo = r0 >> 5;
                #pragma unroll 2
                for (int w = wlo; w < nw32; w++) {
                    int j = (w << 5) + lane, jc = min(j, M - 1);
                    float cx1 = g_bx1[b][jc], cx2 = g_bx2[b][jc];
                    float cy1 = g_by1[b][jc], cy2 = g_by2[b][jc];
                    float cw_ = g_bw [b][jc], ch_ = g_bh [b][jc];
                    #pragma unroll
                    for (int d = 0; d < 4; d++) {
                        int ii = r0 + d;
                        bool sp = (j > ii) && (j < M) && (ii < M) &&
                                  iou_gt(rx1[d], rx2[d], ry1[d], ry2[d], rw[d], rh[d],
                                         cx1, cx2, cy1, cy2, cw_, ch_, 0.45f);
                        unsigned bal = __ballot_sync(0xffffffffu, sp);
                        if (lane == d && ii < M) {
                            mask32[((size_t)(b * NB + ii)) * NW32 + w] = bal;
                            if (w == wlo)   // 8x8 intra byte (diag word)
                                intra8[ii] = (unsigned char)((bal >> (ii & 24)) & 0xFF);
                        }
                    }
                }
            }
        } else {                          // block 0: GT masks + validity
            if (tid == 33) {
                unsigned long long gv = 0ULL;
                int v = 1, tb = 0;
                for (int t = 0; t < 50; t++) {
                    if (sg[t * 5 + 1] == 0.0f) v = 0;
                    gv |= (unsigned long long)v << t; tb += v;
                }
                sGV = gv; sTot = tb;
            }
            unsigned* gtm32 = (unsigned*)g_gtm;
            const int ntasks = 50 * nw32;
            for (int task = warp; task < ntasks; task += 16) {
                int t = task / nw32, w = task - t * nw32;
                float gx = sg[t * 5 + 1], gy = sg[t * 5 + 2];
                float gw = sg[t * 5 + 3], gh = sg[t * 5 + 4];
                float gx1 = gx - gw * 0.5f, gx2 = gx + gw * 0.5f;
                float gy1 = gy - gh * 0.5f, gy2 = gy + gh * 0.5f;
                int j = (w << 5) + lane, jc = min(j, M - 1);
                float cx1 = g_bx1[b][jc], cx2 = g_bx2[b][jc];
                float cy1 = g_by1[b][jc], cy2 = g_by2[b][jc];
                float cw_ = g_bw [b][jc], ch_ = g_bh [b][jc];
                bool sp = (j < M) &&
                          iou_gt(gx1, gx2, gy1, gy2, gw, gh,
                                 cx1, cx2, cy1, cy2, cw_, ch_, 0.5f);
                unsigned bal = __ballot_sync(0xffffffffu, sp);
                if (lane == 0)
                    gtm32[((size_t)(b * 50 + t)) * NW32 + w] = bal;
            }
        }

        __threadfence();
        __syncthreads();
        if (tid == 0) {
            unsigned old = atomicAdd(&g_cntB[b], 1u);
            if (old == BPB - 1) {
                g_cntB[b] = 0;
                __threadfence();
                atomicAdd(&g_relB[b], 1u);
            }
        }
        if (k > 0) return;
        if (tid == 0) { while (*relB == r0b) __nanosleep(64); }
        __syncthreads();
        __threadfence();
    }

    // ================= Phase C (block 0): fast chain + stats =============
    {
        const int M = g_M[b];
        if (tid == 0) sCorr = 0;
        __syncthreads();

        if (warp == 0) {
            const unsigned long long* mb = g_mask + (size_t)b * NB * NW64;
            const unsigned long long* ib = g_intra[b];
            const bool ld = (lane < NW64);
            const int NCH = (M + 7) >> 3;
            unsigned long long removed = 0ULL;
            unsigned long long rowb[3][8], intb[3];
            #pragma unroll
            for (int ph = 0; ph < 3; ph++) {
                intb[ph] = (ph < NCH) ? ib[ph] : 0ULL;
                #pragma unroll
                for (int d = 0; d < 8; d++) {
                    int r = ph * 8 + d;
                    rowb[ph][d] = (ld && r < M) ? mb[(size_t)r * NW64 + lane] : 0ULL;
                }
            }
            for (int c0 = 0; c0 < NCH; c0 += 3) {
                #pragma unroll
                for (int ph = 0; ph < 3; ph++) {
                    int c8 = c0 + ph;
                    if (c8 < NCH) {
                        int c = c8 << 3, w0 = c >> 6, sh = c & 63;
                        unsigned long long rw = __shfl_sync(0xffffffffu, removed, w0);
                        unsigned supp = (unsigned)((rw >> sh) & 0xFFULL);
                        unsigned limm = (M - c >= 8) ? 0xFFu : ((1u << (M - c)) - 1u);
                        unsigned long long intra = intb[ph];
                        unsigned dec;
                        if (intra == 0ULL) {
                            dec = (~supp) & limm;
                        } else {
                            dec = 0;
                            #pragma unroll
                            for (int d = 0; d < 8; d++)
                                if (((limm >> d) & 1u) && !((supp >> d) & 1u)) {
                                    dec  |= 1u << d;
                                    supp |= (unsigned)((intra >> (8 * d)) & 0xFFULL);
                                }
                        }
                        #pragma unroll
                        for (int d = 0; d < 8; d++)
                            if ((dec >> d) & 1u) removed |= rowb[ph][d];
                        int nc = c8 + 3;
                        intb[ph] = (nc < NCH) ? ib[nc] : 0ULL;
                        #pragma unroll
                        for (int d = 0; d < 8; d++) {
                            int r = (nc << 3) + d;
                            rowb[ph][d] = (ld && r < M)
                                        ? mb[(size_t)r * NW64 + lane] : 0ULL;
                        }
                    }
                }
            }
            skeep[lane] = ld ? removed : 0ULL;
            int pc = ld ? __popcll(removed) : 0;
            #pragma unroll
            for (int o = 16; o; o >>= 1) pc += __shfl_xor_sync(0xffffffffu, pc, o);
            if (lane == 0) sProp = M - pc;
        }
        __syncthreads();

        if (tid < 50 && M > 0 && ((sGV >> tid) & 1ULL)) {
            const unsigned long long* gm = g_gtm[b][tid];
            bool any = false;
            #pragma unroll
            for (int w = 0; w < NW64; w++)
                any |= (gm[w] & ~skeep[w]) != 0ULL;
            if (any) atomicAdd(&sCorr, 1);
        }
        __syncthreads();

        if (tid == 0) {
            g_part[b][0] = sTot; g_part[b][1] = sProp; g_part[b][2] = sCorr;
            __threadfence();
            int tk = atomicAdd(&g_ticket, 1);
            if (tk == 7) {
                __threadfence();
                int T = 0, P = 0, C = 0;
                for (int i = 0; i < 8; i++) {
                    T += g_part[i][0]; P += g_part[i][1]; C += g_part[i][2];
                }
                float tf = (float)T, pf = (float)P, cf = (float)C;
                float prec = cf / (pf + 1e-6f);
                float rec  = cf / (tf + 1e-6f);
                float f    = 2.0f * prec * rec / (prec + rec + 1e-6f);
                outp[0] = tf; outp[1] = pf; outp[2] = cf;
                outp[3] = prec; outp[4] = rec; outp[5] = f;
                atomicExch(&g_ticket, 0);
            }
        }
    }
}

extern "C" void kernel_launch(void* const* d_in, const int* in_sizes, int n_in,
                              void* d_out, int out_size) {
    const float* output = (const float*)d_in[0];  // [8,125,19,19]
    const float* target = (const float*)d_in[1];  // [8,250]
    fused_kernel<<<NBLK, NTHR>>>(output, target, (float*)d_out);
}

// round 10
// speedup vs baseline: 1.2025x; 1.1712x over previous
#include <cuda_runtime.h>
#include <math.h>

#define NB     1805          // 5*19*19 boxes per batch
#define NBP    1824
#define NW64   29            // ceil(1805/64) u64 words per mask row
#define NW32   58
#define BPB    38            // blocks per batch
#define NBLK   (8 * BPB)     // 304 >= 148 (avoid low-grid issue throttle)
#define NTHR   256
#define WPB    (BPB * 8)     // warps per batch = 304
#define NCH8   228

// SoA decoded boxes (indexed by rank)
__device__ float g_bx1[8][NBP], g_bx2[8][NBP];
__device__ float g_by1[8][NBP], g_by2[8][NBP];
__device__ float g_bw [8][NBP], g_bh [8][NBP];
__device__ int   g_M[8];
__device__ unsigned long long g_mask[8ULL * NB * NW64];  // zero-init
__device__ unsigned long long g_intra[8][NCH8];          // 8x8 intra-chunk bytes
__device__ unsigned long long g_gtm[8][50][NW64];
__device__ int      g_part[8][3];
__device__ int      g_ticket = 0;
__device__ unsigned g_relA[8], g_cntA[8];
__device__ unsigned g_relB[8], g_cntB[8];

__constant__ float ANCW[5] = {1.3221f, 3.19275f, 5.05587f, 9.47112f, 11.2364f};
__constant__ float ANCH[5] = {1.73145f, 4.00944f, 8.09892f, 4.84053f, 10.0071f};

// IoU > thr with explicit RN ops + IEEE div (matches jax f32; uarea=0 -> NaN -> false)
__device__ __forceinline__ bool iou_gt(
    float ax1, float ax2, float ay1, float ay2, float aw, float ah,
    float bx1, float bx2, float by1, float by2, float bw, float bh, float thr) {
    float uw = __fsub_rn(fmaxf(ax2, bx2), fminf(ax1, bx1));
    float uh = __fsub_rn(fmaxf(ay2, by2), fminf(ay1, by1));
    float cw = __fsub_rn(__fadd_rn(aw, bw), uw);
    float ch = __fsub_rn(__fadd_rn(ah, bh), uh);
    float carea = (cw > 0.0f && ch > 0.0f) ? __fmul_rn(cw, ch) : 0.0f;
    float uarea = __fsub_rn(__fadd_rn(__fmul_rn(aw, ah), __fmul_rn(bw, bh)), carea);
    return __fdiv_rn(carea, uarea) > thr;
}

extern "C" __global__ void __launch_bounds__(NTHR)
fused_kernel(const float* __restrict__ out,    // [8,125,19,19]
             const float* __restrict__ tgt,    // [8,250]
             float* __restrict__ outp)         // [6]
{
    __shared__ unsigned long long slist[NBP + 8];
    __shared__ float sg[252];
    __shared__ unsigned long long skeep[32];
    __shared__ unsigned long long sGV;
    __shared__ int sCnt, sTot, sProp, sCorr;

    const int blk = blockIdx.x;          // 0..303
    const int tid = threadIdx.x;
    const int lane = tid & 31, warp = tid >> 3 >> 2;   // warp = tid>>5
    const int b = blk / BPB, k = blk - b * BPB;

    volatile unsigned* relA = (volatile unsigned*)&g_relA[b];
    volatile unsigned* relB = (volatile unsigned*)&g_relB[b];
    const unsigned r0a = *relA;          // capture at entry (replay-safe)
    const unsigned r0b = *relB;

    // ================= Phase A: compact + split-rank + decode ============
    {
        const float* ob = out + (size_t)b * 125 * 361;
        if (tid == 0) sCnt = 0;
        for (int t = tid; t < 250; t += NTHR) sg[t] = tgt[b * 250 + t];
        __syncthreads();

        // redundant ballot-compact of valid keys as u64 (key<<32 | NB-idx)
        for (int r0 = 0; r0 < NB; r0 += NTHR) {
            int r = r0 + tid;
            bool v = false;
            unsigned long long k64 = 0ULL;
            if (r < NB) {
                int a = r / 361, rem = r - a * 361;
                float kk = ob[(a * 25 + 4) * 361 + rem];
                if (kk > 0.0f) {                      // sigmoid > 0.5
                    v = true;
                    k64 = ((unsigned long long)__float_as_uint(kk) << 32)
                        | (unsigned)(NB - r);
                }
            }
            unsigned bal = __ballot_sync(0xffffffffu, v);
            int base = 0;
            if (lane == 0 && bal) base = atomicAdd(&sCnt, __popc(bal));
            base = __shfl_sync(0xffffffffu, base, 0);
            if (v) slist[base + __popc(bal & ((1u << lane) - 1u))] = k64;
        }
        __syncthreads();
        const int M = sCnt;
        if (k == 0 && tid == 0) g_M[b] = M;
        if (tid < 8) slist[M + tid] = 0ULL;           // pad
        if (tid == 255) {                              // GT validity (off-path)
            unsigned long long gv = 0ULL;
            int v = 1, tb = 0;
            for (int t = 0; t < 50; t++) {
                if (sg[t * 5 + 1] == 0.0f) v = 0;
                gv |= (unsigned long long)v << t; tb += v;
            }
            sGV = gv; sTot = tb;
        }
        __syncthreads();
        const int Mp = (M + 3) & ~3;

        // split rank: 4 threads per box, 48 boxes/block, slice by orig index
        {
            int boxslot = tid >> 2, part = tid & 3;
            int i = k * 48 + boxslot;
            bool act = (boxslot < 48) && (i < NB);
            int a = 0, rem = 0;
            float ki = -1.0f;
            if (act) {
                a = i / 361; rem = i - a * 361;
                ki = ob[(a * 25 + 4) * 361 + rem];
            }
            bool valid = act && (ki > 0.0f);
            int rank = 0;
            if (valid) {
                unsigned long long k64 =
                    ((unsigned long long)__float_as_uint(ki) << 32)
                    | (unsigned)(NB - i);
                const ulonglong2* l2 = (const ulonglong2*)slist;
                int half = Mp >> 1;
                int q = (half + 3) >> 2;
                int wlo = part * q, whi = min(wlo + q, half);
                #pragma unroll 4
                for (int w = wlo; w < whi; w++) {
                    ulonglong2 p = l2[w];
                    rank += (p.x > k64) + (p.y > k64);
                }
            }
            rank += __shfl_xor_sync(0xffffffffu, rank, 1);
            rank += __shfl_xor_sync(0xffffffffu, rank, 2);
            if (valid && part == 0) {
                int hh = rem / 19, ww = rem - hh * 19;
                const float* p = ob + (a * 25) * 361 + rem;
                float cx = (1.0f / (1.0f + expf(-p[0]))   + (float)ww) / 19.0f;
                float cy = (1.0f / (1.0f + expf(-p[361])) + (float)hh) / 19.0f;
                float bw = expf(p[722])  * (ANCW[a] / 19.0f);
                float bh = expf(p[1083]) * (ANCH[a] / 19.0f);
                g_bx1[b][rank] = cx - bw * 0.5f;
                g_bx2[b][rank] = cx + bw * 0.5f;
                g_by1[b][rank] = cy - bh * 0.5f;
                g_by2[b][rank] = cy + bh * 0.5f;
                g_bw [b][rank] = bw;
                g_bh [b][rank] = bh;
            }
        }
        __threadfence();
        __syncthreads();
        if (tid == 0) {
            unsigned old = atomicAdd(&g_cntA[b], 1u);
            if (old == BPB - 1) {
                g_cntA[b] = 0;
                __threadfence();
                atomicAdd(&g_relA[b], 1u);
            }
            while (*relA == r0a) __nanosleep(64);
        }
        __syncthreads();
        __threadfence();
    }

    // ================= Phase B: unified box + GT mask tasks ==============
    {
        const int M = g_M[b];
        const int nw32 = (M + 31) >> 5;
        const int Gbox = (M + 3) >> 2;
        const int Gtot = Gbox + 13;              // + ceil(50/4) GT groups
        unsigned* mask32 = (unsigned*)g_mask;
        unsigned* gtm32  = (unsigned*)g_gtm;
        unsigned char* intra8 = (unsigned char*)&g_intra[b][0];
        const int wq = k * 8 + warp;             // 0..303

        for (int task = wq; task < Gtot; task += WPB) {
            const bool isbox = task < Gbox;
            int r0 = 0, t0 = 0;
            float rx1[4], rx2[4], ry1[4], ry2[4], rw[4], rh[4];
            float thr;
            int wlo;
            if (isbox) {
                r0 = task << 2; thr = 0.45f; wlo = r0 >> 5;
                #pragma unroll
                for (int d = 0; d < 4; d++) {
                    int ii = min(r0 + d, M - 1);
                    rx1[d] = g_bx1[b][ii]; rx2[d] = g_bx2[b][ii];
                    ry1[d] = g_by1[b][ii]; ry2[d] = g_by2[b][ii];
                    rw[d]  = g_bw [b][ii]; rh[d]  = g_bh [b][ii];
                }
            } else {
                t0 = (task - Gbox) << 2; thr = 0.5f; wlo = 0;
                #pragma unroll
                for (int d = 0; d < 4; d++) {
                    int t = min(t0 + d, 49);
                    float gx = sg[t * 5 + 1], gy = sg[t * 5 + 2];
                    float gw = sg[t * 5 + 3], gh = sg[t * 5 + 4];
                    rx1[d] = gx - gw * 0.5f; rx2[d] = gx + gw * 0.5f;
                    ry1[d] = gy - gh * 0.5f; ry2[d] = gy + gh * 0.5f;
                    rw[d]  = gw;             rh[d]  = gh;
                }
            }
            #pragma unroll 2
            for (int w = wlo; w < nw32; w++) {
                int j = (w << 5) + lane, jc = min(j, M - 1);
                float cx1 = g_bx1[b][jc], cx2 = g_bx2[b][jc];
                float cy1 = g_by1[b][jc], cy2 = g_by2[b][jc];
                float cw_ = g_bw [b][jc], ch_ = g_bh [b][jc];
                #pragma unroll
                for (int d = 0; d < 4; d++) {
                    bool sp;
                    if (isbox) {
                        int ii = r0 + d;
                        sp = (j > ii) && (j < M) && (ii < M) &&
                             iou_gt(rx1[d], rx2[d], ry1[d], ry2[d], rw[d], rh[d],
                                    cx1, cx2, cy1, cy2, cw_, ch_, thr);
                    } else {
                        sp = (j < M) && (t0 + d < 50) &&
                             iou_gt(rx1[d], rx2[d], ry1[d], ry2[d], rw[d], rh[d],
                                    cx1, cx2, cy1, cy2, cw_, ch_, thr);
                    }
                    unsigned bal = __ballot_sync(0xffffffffu, sp);
                    if (isbox) {
                        int ii = r0 + d;
                        if (lane == d && ii < M) {
                            mask32[((size_t)(b * NB + ii)) * NW32 + w] = bal;
                            if (w == wlo)
                                intra8[ii] = (unsigned char)((bal >> (ii & 24)) & 0xFF);
                        }
                    } else {
                        int t = t0 + d;
                        if (lane == d && t < 50)
                            gtm32[((size_t)(b * 50 + t)) * NW32 + w] = bal;
                    }
                }
            }
        }

        __threadfence();
        __syncthreads();
        if (tid == 0) {
            unsigned old = atomicAdd(&g_cntB[b], 1u);
            if (old == BPB - 1) {
                g_cntB[b] = 0;
                __threadfence();
                atomicAdd(&g_relB[b], 1u);
            }
        }
        if (k > 0) return;
        if (tid == 0) { while (*relB == r0b) __nanosleep(64); }
        __syncthreads();
        __threadfence();
    }

    // ================= Phase C (block 0 of batch): chain + stats =========
    {
        const int M = g_M[b];
        if (tid == 0) sCorr = 0;
        __syncthreads();

        if (warp == 0) {
            const unsigned long long* mb = g_mask + (size_t)b * NB * NW64;
            const unsigned long long* ib = g_intra[b];
            const bool ld = (lane < NW64);
            const int NCH = (M + 7) >> 3;
            unsigned long long removed = 0ULL;
            unsigned long long rowb[3][8], intb[3];
            #pragma unroll
            for (int ph = 0; ph < 3; ph++) {
                intb[ph] = (ph < NCH) ? ib[ph] : 0ULL;
                #pragma unroll
                for (int d = 0; d < 8; d++) {
                    int r = ph * 8 + d;
                    rowb[ph][d] = (ld && r < M) ? mb[(size_t)r * NW64 + lane] : 0ULL;
                }
            }
            for (int c0 = 0; c0 < NCH; c0 += 3) {
                #pragma unroll
                for (int ph = 0; ph < 3; ph++) {
                    int c8 = c0 + ph;
                    if (c8 < NCH) {
                        int c = c8 << 3, w0 = c >> 6, sh = c & 63;
                        unsigned long long rwv = __shfl_sync(0xffffffffu, removed, w0);
                        unsigned supp = (unsigned)((rwv >> sh) & 0xFFULL);
                        unsigned limm = (M - c >= 8) ? 0xFFu : ((1u << (M - c)) - 1u);
                        unsigned long long intra = intb[ph];
                        unsigned dec;
                        if (intra == 0ULL) {
                            dec = (~supp) & limm;
                        } else {
                            dec = 0;
                            #pragma unroll
                            for (int d = 0; d < 8; d++)
                                if (((limm >> d) & 1u) && !((supp >> d) & 1u)) {
                                    dec  |= 1u << d;
                                    supp |= (unsigned)((intra >> (8 * d)) & 0xFFULL);
                                }
                        }
                        #pragma unroll
                        for (int d = 0; d < 8; d++)
                            if ((dec >> d) & 1u) removed |= rowb[ph][d];
                        int nc = c8 + 3;
                        intb[ph] = (nc < NCH) ? ib[nc] : 0ULL;
                        #pragma unroll
                        for (int d = 0; d < 8; d++) {
                            int r = (nc << 3) + d;
                            rowb[ph][d] = (ld && r < M)
                                        ? mb[(size_t)r * NW64 + lane] : 0ULL;
                        }
                    }
                }
            }
            skeep[lane] = ld ? removed : 0ULL;
            int pc = ld ? __popcll(removed) : 0;
            #pragma unroll
            for (int o = 16; o; o >>= 1) pc += __shfl_xor_sync(0xffffffffu, pc, o);
            if (lane == 0) sProp = M - pc;
        }
        __syncthreads();

        if (tid < 50 && M > 0 && ((sGV >> tid) & 1ULL)) {
            const unsigned long long* gm = g_gtm[b][tid];
            bool any = false;
            #pragma unroll
            for (int w = 0; w < NW64; w++)
                any |= (gm[w] & ~skeep[w]) != 0ULL;
            if (any) atomicAdd(&sCorr, 1);
        }
        __syncthreads();

        if (tid == 0) {
            g_part[b][0] = sTot; g_part[b][1] = sProp; g_part[b][2] = sCorr;
            __threadfence();
            int tk = atomicAdd(&g_ticket, 1);
            if (tk == 7) {
                __threadfence();
                int T = 0, P = 0, C = 0;
                for (int i = 0; i < 8; i++) {
                    T += g_part[i][0]; P += g_part[i][1]; C += g_part[i][2];
                }
                float tf = (float)T, pf = (float)P, cf = (float)C;
                float prec = cf / (pf + 1e-6f);
                float rec  = cf / (tf + 1e-6f);
                float f    = 2.0f * prec * rec / (prec + rec + 1e-6f);
                outp[0] = tf; outp[1] = pf; outp[2] = cf;
                outp[3] = prec; outp[4] = rec; outp[5] = f;
                atomicExch(&g_ticket, 0);
            }
        }
    }
}

extern "C" void kernel_launch(void* const* d_in, const int* in_sizes, int n_in,
                              void* d_out, int out_size) {
    const float* output = (const float*)d_in[0];  // [8,125,19,19]
    const float* target = (const float*)d_in[1];  // [8,250]
    fused_kernel<<<NBLK, NTHR>>>(output, target, (float*)d_out);
}

// round 11
// speedup vs baseline: 1.2587x; 1.0468x over previous
#include <cuda_runtime.h>
#include <math.h>

#define NB     1805          // 5*19*19 boxes per batch
#define NBP    1824
#define NW64   29            // ceil(1805/64) u64 words per mask row
#define NW32   58
#define BPB    38            // blocks per batch
#define NBLK   (8 * BPB)     // 304 >= 148 (avoid low-grid issue throttle)
#define NTHR   256
#define WPB    (BPB * 8)     // warps per batch = 304
#define NCH8   228
#define NBUCK  2048          // key bucket count (float bits >> 20)

// SoA decoded boxes (indexed by rank)
__device__ float g_bx1[8][NBP], g_bx2[8][NBP];
__device__ float g_by1[8][NBP], g_by2[8][NBP];
__device__ float g_bw [8][NBP], g_bh [8][NBP];
__device__ int   g_M[8];
__device__ unsigned long long g_mask[8ULL * NB * NW64];  // zero-init
__device__ unsigned long long g_intra[8][NCH8];          // 8x8 intra-chunk bytes
__device__ unsigned long long g_gtm[8][50][NW64];
__device__ int      g_part[8][3];
__device__ int      g_ticket = 0;
__device__ unsigned g_relA[8], g_cntA[8];
__device__ unsigned g_relB[8], g_cntB[8];

__constant__ float ANCW[5] = {1.3221f, 3.19275f, 5.05587f, 9.47112f, 11.2364f};
__constant__ float ANCH[5] = {1.73145f, 4.00944f, 8.09892f, 4.84053f, 10.0071f};

// IoU > thr with explicit RN ops + IEEE div (matches jax f32; uarea=0 -> NaN -> false)
__device__ __forceinline__ bool iou_gt(
    float ax1, float ax2, float ay1, float ay2, float aw, float ah,
    float bx1, float bx2, float by1, float by2, float bw, float bh, float thr) {
    float uw = __fsub_rn(fmaxf(ax2, bx2), fminf(ax1, bx1));
    float uh = __fsub_rn(fmaxf(ay2, by2), fminf(ay1, by1));
    float cw = __fsub_rn(__fadd_rn(aw, bw), uw);
    float ch = __fsub_rn(__fadd_rn(ah, bh), uh);
    float carea = (cw > 0.0f && ch > 0.0f) ? __fmul_rn(cw, ch) : 0.0f;
    float uarea = __fsub_rn(__fadd_rn(__fmul_rn(aw, ah), __fmul_rn(bw, bh)), carea);
    return __fdiv_rn(carea, uarea) > thr;
}

extern "C" __global__ void __launch_bounds__(NTHR)
fused_kernel(const float* __restrict__ out,    // [8,125,19,19]
             const float* __restrict__ tgt,    // [8,250]
             float* __restrict__ outp)         // [6]
{
    __shared__ unsigned hist[NBUCK];           // counts -> in-seg excl suffix
    __shared__ unsigned cnt [NBUCK];           // scatter cursors / bucket sizes
    __shared__ unsigned spart[NTHR];           // per-segment totals -> scan
    __shared__ unsigned long long sgrp[NBP];   // bucket-grouped (key||NB-idx)
    __shared__ float sg[252];
    __shared__ unsigned long long skeep[32];
    __shared__ unsigned long long sGV;
    __shared__ int sCnt, sTot, sProp, sCorr;

    const int blk = blockIdx.x;          // 0..303
    const int tid = threadIdx.x;
    const int lane = tid & 31, warp = tid >> 5;
    const int b = blk / BPB, k = blk - b * BPB;

    volatile unsigned* relA = (volatile unsigned*)&g_relA[b];
    volatile unsigned* relB = (volatile unsigned*)&g_relB[b];
    const unsigned r0a = *relA;          // capture at entry (replay-safe)
    const unsigned r0b = *relB;

    // ================= Phase A: counting-sort rank + decode ==============
    {
        const float* ob = out + (size_t)b * 125 * 361;
        for (int i = tid; i < NBUCK; i += NTHR) { hist[i] = 0; cnt[i] = 0; }
        for (int t = tid; t < 250; t += NTHR) sg[t] = tgt[b * 250 + t];
        __syncthreads();

        // pass 1: bucket histogram of valid keys (positive logits)
        for (int r = tid; r < NB; r += NTHR) {
            int a = r / 361, rem = r - a * 361;
            float kk = ob[(a * 25 + 4) * 361 + rem];
            if (kk > 0.0f)
                atomicAdd(&hist[__float_as_uint(kk) >> 20], 1u);
        }
        if (k == 0 && tid == 255) {              // GT validity (off-path)
            unsigned long long gv = 0ULL;
            int v = 1, tb = 0;
            for (int t = 0; t < 50; t++) {
                if (sg[t * 5 + 1] == 0.0f) v = 0;
                gv |= (unsigned long long)v << t; tb += v;
            }
            sGV = gv; sTot = tb;
        }
        __syncthreads();

        // exclusive suffix over segments of 8 buckets (in-place)
        {
            unsigned run = 0;
            int s0 = tid * 8;
            #pragma unroll
            for (int i = 7; i >= 0; i--) {
                unsigned c = hist[s0 + i];
                hist[s0 + i] = run;
                run += c;
            }
            spart[tid] = run;
        }
        __syncthreads();
        if (warp == 0) {                         // suffix-scan of 256 partials
            unsigned v[8], run2 = 0;
            #pragma unroll
            for (int i = 7; i >= 0; i--) {
                unsigned c = spart[lane * 8 + i];
                v[i] = run2; run2 += c;
            }
            unsigned x = run2;
            #pragma unroll
            for (int off = 1; off < 32; off <<= 1) {
                unsigned y = __shfl_down_sync(0xffffffffu, x, off);
                if (lane + off < 32) x += y;
            }
            unsigned excl = x - run2;
            #pragma unroll
            for (int i = 0; i < 8; i++) spart[lane * 8 + i] = v[i] + excl;
            if (lane == 0) sCnt = (int)x;        // M = total valid
        }
        __syncthreads();
        const int M = sCnt;
        if (k == 0 && tid == 0) g_M[b] = M;

        // pass 2: bucket-grouped scatter (order within bucket irrelevant)
        for (int r = tid; r < NB; r += NTHR) {
            int a = r / 361, rem = r - a * 361;
            float kk = ob[(a * 25 + 4) * 361 + rem];
            if (kk > 0.0f) {
                unsigned kb = __float_as_uint(kk);
                unsigned bu = kb >> 20;
                unsigned slot = hist[bu] + spart[bu >> 3] + atomicAdd(&cnt[bu], 1u);
                sgrp[slot] = ((unsigned long long)kb << 32) | (unsigned)(NB - r);
            }
        }
        __syncthreads();

        // pass 3: rank + decode my 48 boxes (1 thread/box)
        if (tid < 48) {
            int i = k * 48 + tid;
            if (i < NB) {
                int a = i / 361, rem = i - a * 361;
                float ki = ob[(a * 25 + 4) * 361 + rem];
                if (ki > 0.0f) {
                    unsigned kb = __float_as_uint(ki);
                    unsigned bu = kb >> 20;
                    unsigned base = hist[bu] + spart[bu >> 3];
                    unsigned c = cnt[bu];
                    unsigned long long k64 =
                        ((unsigned long long)kb << 32) | (unsigned)(NB - i);
                    int rank = (int)base;
                    for (unsigned q = 0; q < c; q++)
                        rank += (sgrp[base + q] > k64);
                    int hh = rem / 19, ww = rem - hh * 19;
                    const float* p = ob + (a * 25) * 361 + rem;
                    float cx = (1.0f / (1.0f + expf(-p[0]))   + (float)ww) / 19.0f;
                    float cy = (1.0f / (1.0f + expf(-p[361])) + (float)hh) / 19.0f;
                    float bw = expf(p[722])  * (ANCW[a] / 19.0f);
                    float bh = expf(p[1083]) * (ANCH[a] / 19.0f);
                    g_bx1[b][rank] = cx - bw * 0.5f;
                    g_bx2[b][rank] = cx + bw * 0.5f;
                    g_by1[b][rank] = cy - bh * 0.5f;
                    g_by2[b][rank] = cy + bh * 0.5f;
                    g_bw [b][rank] = bw;
                    g_bh [b][rank] = bh;
                }
            }
        }
        __threadfence();
        __syncthreads();
        if (tid == 0) {
            unsigned old = atomicAdd(&g_cntA[b], 1u);
            if (old == BPB - 1) {
                g_cntA[b] = 0;
                __threadfence();
                atomicAdd(&g_relA[b], 1u);
            }
            while (*relA == r0a) __nanosleep(64);
        }
        __syncthreads();
        __threadfence();
    }

    // ================= Phase B: unified box + GT mask tasks ==============
    {
        const int M = g_M[b];
        const int nw32 = (M + 31) >> 5;
        const int Gbox = (M + 3) >> 2;
        const int Gtot = Gbox + 13;              // + ceil(50/4) GT groups
        unsigned* mask32 = (unsigned*)g_mask;
        unsigned* gtm32  = (unsigned*)g_gtm;
        unsigned char* intra8 = (unsigned char*)&g_intra[b][0];
        const int wq = k * 8 + warp;             // 0..303

        for (int task = wq; task < Gtot; task += WPB) {
            const bool isbox = task < Gbox;
            int r0 = 0, t0 = 0;
            float rx1[4], rx2[4], ry1[4], ry2[4], rw[4], rh[4];
            float thr;
            int wlo;
            if (isbox) {
                r0 = task << 2; thr = 0.45f; wlo = r0 >> 5;
                #pragma unroll
                for (int d = 0; d < 4; d++) {
                    int ii = min(r0 + d, NBP - 1);
                    rx1[d] = g_bx1[b][ii]; rx2[d] = g_bx2[b][ii];
                    ry1[d] = g_by1[b][ii]; ry2[d] = g_by2[b][ii];
                    rw[d]  = g_bw [b][ii]; rh[d]  = g_bh [b][ii];
                }
            } else {
                t0 = (task - Gbox) << 2; thr = 0.5f; wlo = 0;
                #pragma unroll
                for (int d = 0; d < 4; d++) {
                    int t = min(t0 + d, 49);
                    float gx = sg[t * 5 + 1], gy = sg[t * 5 + 2];
                    float gw = sg[t * 5 + 3], gh = sg[t * 5 + 4];
                    rx1[d] = gx - gw * 0.5f; rx2[d] = gx + gw * 0.5f;
                    ry1[d] = gy - gh * 0.5f; ry2[d] = gy + gh * 0.5f;
                    rw[d]  = gw;             rh[d]  = gh;
                }
            }
            #pragma unroll 2
            for (int w = wlo; w < nw32; w++) {
                int j = (w << 5) + lane;         // reads < NBP always in-bounds
                float cx1 = g_bx1[b][j], cx2 = g_bx2[b][j];
                float cy1 = g_by1[b][j], cy2 = g_by2[b][j];
                float cw_ = g_bw [b][j], ch_ = g_bh [b][j];
                #pragma unroll
                for (int d = 0; d < 4; d++) {
                    bool sp;
                    if (isbox) {
                        int ii = r0 + d;
                        sp = (j > ii) && (j < M) && (ii < M) &&
                             iou_gt(rx1[d], rx2[d], ry1[d], ry2[d], rw[d], rh[d],
                                    cx1, cx2, cy1, cy2, cw_, ch_, thr);
                    } else {
                        sp = (j < M) && (t0 + d < 50) &&
                             iou_gt(rx1[d], rx2[d], ry1[d], ry2[d], rw[d], rh[d],
                                    cx1, cx2, cy1, cy2, cw_, ch_, thr);
                    }
                    unsigned bal = __ballot_sync(0xffffffffu, sp);
                    if (isbox) {
                        int ii = r0 + d;
                        if (lane == d && ii < M) {
                            mask32[((size_t)(b * NB + ii)) * NW32 + w] = bal;
                            if (w == wlo)
                                intra8[ii] = (unsigned char)((bal >> (ii & 24)) & 0xFF);
                        }
                    } else {
                        int t = t0 + d;
                        if (lane == d && t < 50)
                            gtm32[((size_t)(b * 50 + t)) * NW32 + w] = bal;
                    }
                }
            }
        }

        __threadfence();
        __syncthreads();
        if (tid == 0) {
            unsigned old = atomicAdd(&g_cntB[b], 1u);
            if (old == BPB - 1) {
                g_cntB[b] = 0;
                __threadfence();
                atomicAdd(&g_relB[b], 1u);
            }
        }
        if (k > 0) return;
        if (tid == 0) { while (*relB == r0b) __nanosleep(64); }
        __syncthreads();
        __threadfence();
    }

    // ================= Phase C (block 0 of batch): chain + stats =========
    {
        const int M = g_M[b];
        if (tid == 0) sCorr = 0;
        __syncthreads();

        if (warp == 0) {
            const unsigned long long* mb = g_mask + (size_t)b * NB * NW64;
            const unsigned long long* ib = g_intra[b];
            const bool ld = (lane < NW64);
            const int NCH = (M + 7) >> 3;
            unsigned long long removed = 0ULL;
            unsigned long long rowb[3][8], intb[3];
            #pragma unroll
            for (int ph = 0; ph < 3; ph++) {
                intb[ph] = (ph < NCH) ? ib[ph] : 0ULL;
                #pragma unroll
                for (int d = 0; d < 8; d++) {
                    int r = ph * 8 + d;
                    rowb[ph][d] = (ld && r < M) ? mb[(size_t)r * NW64 + lane] : 0ULL;
                }
            }
            for (int c0 = 0; c0 < NCH; c0 += 3) {
                #pragma unroll
                for (int ph = 0; ph < 3; ph++) {
                    int c8 = c0 + ph;
                    if (c8 < NCH) {
                        int c = c8 << 3, w0 = c >> 6, sh = c & 63;
                        unsigned long long rwv = __shfl_sync(0xffffffffu, removed, w0);
                        unsigned supp = (unsigned)((rwv >> sh) & 0xFFULL);
                        unsigned limm = (M - c >= 8) ? 0xFFu : ((1u << (M - c)) - 1u);
                        unsigned long long intra = intb[ph];
                        unsigned dec;
                        if (intra == 0ULL) {
                            dec = (~supp) & limm;
                        } else {
                            dec = 0;
                            #pragma unroll
                            for (int d = 0; d < 8; d++)
                                if (((limm >> d) & 1u) && !((supp >> d) & 1u)) {
                                    dec  |= 1u << d;
                                    supp |= (unsigned)((intra >> (8 * d)) & 0xFFULL);
                                }
                        }
                        #pragma unroll
                        for (int d = 0; d < 8; d++)
                            if ((dec >> d) & 1u) removed |= rowb[ph][d];
                        int nc = c8 + 3;
                        intb[ph] = (nc < NCH) ? ib[nc] : 0ULL;
                        #pragma unroll
                        for (int d = 0; d < 8; d++) {
                            int r = (nc << 3) + d;
                            rowb[ph][d] = (ld && r < M)
                                        ? mb[(size_t)r * NW64 + lane] : 0ULL;
                        }
                    }
                }
            }
            skeep[lane] = ld ? removed : 0ULL;
            int pc = ld ? __popcll(removed) : 0;
            #pragma unroll
            for (int o = 16; o; o >>= 1) pc += __shfl_xor_sync(0xffffffffu, pc, o);
            if (lane == 0) sProp = M - pc;
        }
        __syncthreads();

        if (tid < 50 && M > 0 && ((sGV >> tid) & 1ULL)) {
            const unsigned long long* gm = g_gtm[b][tid];
            bool any = false;
            #pragma unroll
            for (int w = 0; w < NW64; w++)
                any |= (gm[w] & ~skeep[w]) != 0ULL;
            if (any) atomicAdd(&sCorr, 1);
        }
        __syncthreads();

        if (tid == 0) {
            g_part[b][0] = sTot; g_part[b][1] = sProp; g_part[b][2] = sCorr;
            __threadfence();
            int tk = atomicAdd(&g_ticket, 1);
            if (tk == 7) {
                __threadfence();
                int T = 0, P = 0, C = 0;
                for (int i = 0; i < 8; i++) {
                    T += g_part[i][0]; P += g_part[i][1]; C += g_part[i][2];
                }
                float tf = (float)T, pf = (float)P, cf = (float)C;
                float prec = cf / (pf + 1e-6f);
                float rec  = cf / (tf + 1e-6f);
                float f    = 2.0f * prec * rec / (prec + rec + 1e-6f);
                outp[0] = tf; outp[1] = pf; outp[2] = cf;
                outp[3] = prec; outp[4] = rec; outp[5] = f;
                atomicExch(&g_ticket, 0);
            }
        }
    }
}

extern "C" void kernel_launch(void* const* d_in, const int* in_sizes, int n_in,
                              void* d_out, int out_size) {
    const float* output = (const float*)d_in[0];  // [8,125,19,19]
    const float* target = (const float*)d_in[1];  // [8,250]
    fused_kernel<<<NBLK, NTHR>>>(output, target, (float*)d_out);
}

// round 12
// speedup vs baseline: 1.3557x; 1.0770x over previous
#include <cuda_runtime.h>
#include <math.h>

#define NB     1805          // 5*19*19 boxes per batch
#define NBP    1824
#define NW64   29            // ceil(1805/64) u64 words per mask row
#define NW32   58
#define BPB    37            // blocks per batch
#define NBLK   (8 * BPB)     // 296 = 2/SM co-resident, >=148 (no low-grid throttle)
#define NTHR   256
#define WPB    (BPB * 8)     // warps per batch = 296
#define NCH8   228
#define NBUCK  2048          // key bucket count (float bits >> 20)

// decoded boxes (indexed by rank): corners packed, w/h packed
__device__ float4 g_box4[8][NBP];                        // x1,x2,y1,y2
__device__ float2 g_bwh [8][NBP];                        // w,h
__device__ int   g_M[8];
__device__ unsigned long long g_mask[8ULL * NB * NW64];  // zero-init
__device__ unsigned long long g_intra[8][NCH8];          // 8x8 intra-chunk bytes
__device__ unsigned long long g_gtm[8][50][NW64];
__device__ int      g_part[8][3];
__device__ int      g_ticket = 0;
__device__ unsigned g_relA[8], g_cntA[8];
__device__ unsigned g_relB[8], g_cntB[8];

__constant__ float ANCW[5] = {1.3221f, 3.19275f, 5.05587f, 9.47112f, 11.2364f};
__constant__ float ANCH[5] = {1.73145f, 4.00944f, 8.09892f, 4.84053f, 10.0071f};

// IoU > thr with explicit RN ops + IEEE div (matches jax f32; uarea=0 -> NaN -> false)
__device__ __forceinline__ bool iou_gt(
    float ax1, float ax2, float ay1, float ay2, float aw, float ah,
    float bx1, float bx2, float by1, float by2, float bw, float bh, float thr) {
    float uw = __fsub_rn(fmaxf(ax2, bx2), fminf(ax1, bx1));
    float uh = __fsub_rn(fmaxf(ay2, by2), fminf(ay1, by1));
    float cw = __fsub_rn(__fadd_rn(aw, bw), uw);
    float ch = __fsub_rn(__fadd_rn(ah, bh), uh);
    float carea = (cw > 0.0f && ch > 0.0f) ? __fmul_rn(cw, ch) : 0.0f;
    float uarea = __fsub_rn(__fadd_rn(__fmul_rn(aw, ah), __fmul_rn(bw, bh)), carea);
    return __fdiv_rn(carea, uarea) > thr;
}

extern "C" __global__ void __launch_bounds__(NTHR, 2)
fused_kernel(const float* __restrict__ out,    // [8,125,19,19]
             const float* __restrict__ tgt,    // [8,250]
             float* __restrict__ outp)         // [6]
{
    __shared__ unsigned hist[NBUCK];           // counts -> global desc-CDF base
    __shared__ unsigned cnt [NBUCK];           // scatter cursors / bucket sizes
    __shared__ unsigned spart[NTHR];           // per-segment totals -> scan
    __shared__ unsigned long long sgrp[NBP];   // bucket-grouped (key||NB-idx)
    __shared__ float sg[252];
    __shared__ unsigned long long skeep[32];
    __shared__ unsigned long long sGV;
    __shared__ int sTot, sProp, sCorr;

    const int blk = blockIdx.x;          // 0..295
    const int tid = threadIdx.x;
    const int lane = tid & 31, warp = tid >> 5;
    const int b = blk / BPB, k = blk - b * BPB;

    volatile unsigned* relA = (volatile unsigned*)&g_relA[b];
    volatile unsigned* relB = (volatile unsigned*)&g_relB[b];
    const unsigned r0a = *relA;          // capture at entry (replay-safe)
    const unsigned r0b = *relB;

    // ================= Phase A: 1-pass counting-sort rank + decode =======
    {
        const float* ob = out + (size_t)b * 125 * 361;
        for (int i = tid; i < NBUCK; i += NTHR) { hist[i] = 0; cnt[i] = 0; }
        for (int t = tid; t < 250; t += NTHR) sg[t] = tgt[b * 250 + t];

        // single global pass: keys into registers
        unsigned kb[8];
        #pragma unroll
        for (int it = 0; it < 8; it++) {
            int r = it * NTHR + tid;
            kb[it] = 0;
            if (r < NB) {
                int a = r / 361, rem = r - a * 361;
                float kk = ob[(a * 25 + 4) * 361 + rem];
                if (kk > 0.0f) kb[it] = __float_as_uint(kk);   // >0 => valid
            }
        }
        __syncthreads();
        #pragma unroll
        for (int it = 0; it < 8; it++)
            if (kb[it]) atomicAdd(&hist[kb[it] >> 20], 1u);
        if (k == 0 && tid == 255) {              // GT validity (off-path)
            unsigned long long gv = 0ULL;
            int v = 1, tb = 0;
            for (int t = 0; t < 50; t++) {
                if (sg[t * 5 + 1] == 0.0f) v = 0;
                gv |= (unsigned long long)v << t; tb += v;
            }
            sGV = gv; sTot = tb;
        }
        __syncthreads();

        // in-segment exclusive suffix (8 buckets/thread)
        {
            unsigned run = 0;
            int s0 = tid * 8;
            #pragma unroll
            for (int i = 7; i >= 0; i--) {
                unsigned c = hist[s0 + i];
                hist[s0 + i] = run;
                run += c;
            }
            spart[tid] = run;
        }
        __syncthreads();
        if (warp == 0) {                         // suffix-scan of 256 partials
            unsigned v[8], run2 = 0;
            #pragma unroll
            for (int i = 7; i >= 0; i--) {
                unsigned c = spart[lane * 8 + i];
                v[i] = run2; run2 += c;
            }
            unsigned x = run2;
            #pragma unroll
            for (int off = 1; off < 32; off <<= 1) {
                unsigned y = __shfl_down_sync(0xffffffffu, x, off);
                if (lane + off < 32) x += y;
            }
            unsigned excl = x - run2;
            #pragma unroll
            for (int i = 0; i < 8; i++) spart[lane * 8 + i] = v[i] + excl;
            if (lane == 0) { g_M[b] = (int)x; }  // every block writes same M
        }
        __syncthreads();
        // merge cross-segment base into hist -> hist[bu] = #keys in buckets > bu
        {
            unsigned base = spart[tid];
            int s0 = tid * 8;
            #pragma unroll
            for (int i = 0; i < 8; i++) hist[s0 + i] += base;
        }
        __syncthreads();
        const int M = g_M[b];

        // scatter from registers (order within bucket irrelevant)
        #pragma unroll
        for (int it = 0; it < 8; it++) {
            if (kb[it]) {
                int r = it * NTHR + tid;
                unsigned bu = kb[it] >> 20;
                unsigned slot = hist[bu] + atomicAdd(&cnt[bu], 1u);
                sgrp[slot] = ((unsigned long long)kb[it] << 32) | (unsigned)(NB - r);
            }
        }
        __syncthreads();

        // rank + decode my 49 boxes (1 thread/box)
        if (tid < 49) {
            int i = k * 49 + tid;
            if (i < NB) {
                int a = i / 361, rem = i - a * 361;
                float ki = ob[(a * 25 + 4) * 361 + rem];
                if (ki > 0.0f) {
                    unsigned kbb = __float_as_uint(ki);
                    unsigned bu = kbb >> 20;
                    unsigned base = hist[bu];
                    unsigned c = cnt[bu];
                    unsigned long long k64 =
                        ((unsigned long long)kbb << 32) | (unsigned)(NB - i);
                    int rank = (int)base;
                    for (unsigned q = 0; q < c; q++)
                        rank += (sgrp[base + q] > k64);
                    int hh = rem / 19, ww = rem - hh * 19;
                    const float* p = ob + (a * 25) * 361 + rem;
                    float cx = (1.0f / (1.0f + expf(-p[0]))   + (float)ww) / 19.0f;
                    float cy = (1.0f / (1.0f + expf(-p[361])) + (float)hh) / 19.0f;
                    float bw = expf(p[722])  * (ANCW[a] / 19.0f);
                    float bh = expf(p[1083]) * (ANCH[a] / 19.0f);
                    g_box4[b][rank] = make_float4(cx - bw * 0.5f, cx + bw * 0.5f,
                                                  cy - bh * 0.5f, cy + bh * 0.5f);
                    g_bwh [b][rank] = make_float2(bw, bh);
                }
            }
        }
        __threadfence();
        __syncthreads();
        if (tid == 0) {
            unsigned old = atomicAdd(&g_cntA[b], 1u);
            if (old == BPB - 1) {
                g_cntA[b] = 0;
                __threadfence();
                atomicAdd(&g_relA[b], 1u);
            }
            while (*relA == r0a) __nanosleep(32);
        }
        __syncthreads();
        __threadfence();
    }

    // ================= Phase B: parity-split box + GT mask tasks =========
    {
        const int M = g_M[b];
        const int nw32 = (M + 31) >> 5;
        const int Gbox = (M + 3) >> 2;
        const int Gtot = 2 * Gbox + 26;          // paired box tasks + 13x2 GT
        unsigned* mask32 = (unsigned*)g_mask;
        unsigned* gtm32  = (unsigned*)g_gtm;
        unsigned char* intra8 = (unsigned char*)&g_intra[b][0];
        const int wq = k * 8 + warp;             // 0..295

        for (int task = wq; task < Gtot; task += WPB) {
            const bool isbox = task < 2 * Gbox;
            int r0 = 0, t0 = 0, par, wlo;
            float rx1[4], rx2[4], ry1[4], ry2[4], rw[4], rh[4];
            float thr;
            if (isbox) {
                int g = task >> 1; par = task & 1;
                r0 = g << 2; thr = 0.45f; wlo = r0 >> 5;
                #pragma unroll
                for (int d = 0; d < 4; d++) {
                    int ii = min(r0 + d, NBP - 1);
                    float4 B4 = g_box4[b][ii];
                    float2 WH = g_bwh [b][ii];
                    rx1[d] = B4.x; rx2[d] = B4.y; ry1[d] = B4.z; ry2[d] = B4.w;
                    rw[d] = WH.x; rh[d] = WH.y;
                }
            } else {
                int idx = task - 2 * Gbox;
                int tg = idx >> 1; par = idx & 1;
                t0 = tg << 2; thr = 0.5f; wlo = 0;
                #pragma unroll
                for (int d = 0; d < 4; d++) {
                    int t = min(t0 + d, 49);
                    float gx = sg[t * 5 + 1], gy = sg[t * 5 + 2];
                    float gw = sg[t * 5 + 3], gh = sg[t * 5 + 4];
                    rx1[d] = gx - gw * 0.5f; rx2[d] = gx + gw * 0.5f;
                    ry1[d] = gy - gh * 0.5f; ry2[d] = gy + gh * 0.5f;
                    rw[d]  = gw;             rh[d]  = gh;
                }
            }
            for (int w = wlo + par; w < nw32; w += 2) {
                int j = (w << 5) + lane;         // reads < NBP always in-bounds
                float4 C4 = g_box4[b][j];
                float2 CW = g_bwh [b][j];
                #pragma unroll
                for (int d = 0; d < 4; d++) {
                    bool sp;
                    if (isbox) {
                        int ii = r0 + d;
                        sp = (j > ii) && (j < M) && (ii < M) &&
                             iou_gt(rx1[d], rx2[d], ry1[d], ry2[d], rw[d], rh[d],
                                    C4.x, C4.y, C4.z, C4.w, CW.x, CW.y, thr);
                    } else {
                        sp = (j < M) && (t0 + d < 50) &&
                             iou_gt(rx1[d], rx2[d], ry1[d], ry2[d], rw[d], rh[d],
                                    C4.x, C4.y, C4.z, C4.w, CW.x, CW.y, thr);
                    }
                    unsigned bal = __ballot_sync(0xffffffffu, sp);
                    if (isbox) {
                        int ii = r0 + d;
                        if (lane == d && ii < M) {
                            mask32[((size_t)(b * NB + ii)) * NW32 + w] = bal;
                            if (w == wlo)        // parity 0 owns the diag word
                                intra8[ii] = (unsigned char)((bal >> (ii & 24)) & 0xFF);
                        }
                    } else {
                        int t = t0 + d;
                        if (lane == d && t < 50)
                            gtm32[((size_t)(b * 50 + t)) * NW32 + w] = bal;
                    }
                }
            }
        }

        __threadfence();
        __syncthreads();
        if (tid == 0) {
            unsigned old = atomicAdd(&g_cntB[b], 1u);
            if (old == BPB - 1) {
                g_cntB[b] = 0;
                __threadfence();
                atomicAdd(&g_relB[b], 1u);
            }
        }
        if (k > 0) return;
        if (tid == 0) { while (*relB == r0b) __nanosleep(32); }
        __syncthreads();
        __threadfence();
    }

    // ================= Phase C (block 0 of batch): chain + stats =========
    {
        const int M = g_M[b];
        if (tid == 0) sCorr = 0;
        __syncthreads();

        if (warp == 0) {
            const unsigned long long* mb = g_mask + (size_t)b * NB * NW64;
            const unsigned long long* ib = g_intra[b];
            const bool ld = (lane < NW64);
            const int NCH = (M + 7) >> 3;
            unsigned long long removed = 0ULL;
            unsigned long long rowb[3][8], intb[3];
            #pragma unroll
            for (int ph = 0; ph < 3; ph++) {
                intb[ph] = (ph < NCH) ? ib[ph] : 0ULL;
                #pragma unroll
                for (int d = 0; d < 8; d++) {
                    int r = ph * 8 + d;
                    rowb[ph][d] = (ld && r < M) ? mb[(size_t)r * NW64 + lane] : 0ULL;
                }
            }
            for (int c0 = 0; c0 < NCH; c0 += 3) {
                #pragma unroll
                for (int ph = 0; ph < 3; ph++) {
                    int c8 = c0 + ph;
                    if (c8 < NCH) {
                        int c = c8 << 3, w0 = c >> 6, sh = c & 63;
                        unsigned long long rwv = __shfl_sync(0xffffffffu, removed, w0);
                        unsigned supp = (unsigned)((rwv >> sh) & 0xFFULL);
                        unsigned limm = (M - c >= 8) ? 0xFFu : ((1u << (M - c)) - 1u);
                        unsigned long long intra = intb[ph];
                        unsigned dec;
                        if (intra == 0ULL) {
                            dec = (~supp) & limm;
                        } else {
                            dec = 0;
                            #pragma unroll
                            for (int d = 0; d < 8; d++)
                                if (((limm >> d) & 1u) && !((supp >> d) & 1u)) {
                                    dec  |= 1u << d;
                                    supp |= (unsigned)((intra >> (8 * d)) & 0xFFULL);
                                }
                        }
                        #pragma unroll
                        for (int d = 0; d < 8; d++)
                            if ((dec >> d) & 1u) removed |= rowb[ph][d];
                        int nc = c8 + 3;
                        intb[ph] = (nc < NCH) ? ib[nc] : 0ULL;
                        #pragma unroll
                        for (int d = 0; d < 8; d++) {
                            int r = (nc << 3) + d;
                            rowb[ph][d] = (ld && r < M)
                                        ? mb[(size_t)r * NW64 + lane] : 0ULL;
                        }
                    }
                }
            }
            skeep[lane] = ld ? removed : 0ULL;
            int pc = ld ? __popcll(removed) : 0;
            #pragma unroll
            for (int o = 16; o; o >>= 1) pc += __shfl_xor_sync(0xffffffffu, pc, o);
            if (lane == 0) sProp = M - pc;
        }
        __syncthreads();

        if (tid < 50 && M > 0 && ((sGV >> tid) & 1ULL)) {
            const unsigned long long* gm = g_gtm[b][tid];
            bool any = false;
            #pragma unroll
            for (int w = 0; w < NW64; w++)
                any |= (gm[w] & ~skeep[w]) != 0ULL;
            if (any) atomicAdd(&sCorr, 1);
        }
        __syncthreads();

        if (tid == 0) {
            g_part[b][0] = sTot; g_part[b][1] = sProp; g_part[b][2] = sCorr;
            __threadfence();
            int tk = atomicAdd(&g_ticket, 1);
            if (tk == 7) {
                __threadfence();
                int T = 0, P = 0, C = 0;
                for (int i = 0; i < 8; i++) {
                    T += g_part[i][0]; P += g_part[i][1]; C += g_part[i][2];
                }
                float tf = (float)T, pf = (float)P, cf = (float)C;
                float prec = cf / (pf + 1e-6f);
                float rec  = cf / (tf + 1e-6f);
                float f    = 2.0f * prec * rec / (prec + rec + 1e-6f);
                outp[0] = tf; outp[1] = pf; outp[2] = cf;
                outp[3] = prec; outp[4] = rec; outp[5] = f;
                atomicExch(&g_ticket, 0);
            }
        }
    }
}

extern "C" void kernel_launch(void* const* d_in, const int* in_sizes, int n_in,
                              void* d_out, int out_size) {
    const float* output = (const float*)d_in[0];  // [8,125,19,19]
    const float* target = (const float*)d_in[1];  // [8,250]
    fused_kernel<<<NBLK, NTHR>>>(output, target, (float*)d_out);
}